// round 4
// baseline (speedup 1.0000x reference)
#include <cuda_runtime.h>
#include <cuda_bf16.h>

#define G     64
#define NVOX  (G*G*G)
#define INC   32
#define OUTC  64
#define TZ    16

// ---- device scratch (allocation-free rule: static __device__ arrays) ----
__device__ float g_voxsum[NVOX * INC];   // 32 MB: scatter sums, normalized in place
__device__ float g_cnt[NVOX];            //  1 MB: per-voxel point counts
__device__ float g_conv[NVOX * OUTC];    // 64 MB: conv output

// ============================================================================
// 1) scatter-mean accumulate: per point, vector atomics into its voxel
// ============================================================================
__global__ void scatter_kernel(const float* __restrict__ pts,
                               const float* __restrict__ feats, int n) {
    int i = blockIdx.x * blockDim.x + threadIdx.x;
    if (i >= n) return;
    float px = pts[3 * i + 0];
    float py = pts[3 * i + 1];
    float pz = pts[3 * i + 2];
    int bx = (int)floorf(px);
    int by = (int)floorf(py);
    int bz = (int)floorf(pz);
    bx = min(max(bx, 0), G - 1);
    by = min(max(by, 0), G - 1);
    bz = min(max(bz, 0), G - 1);
    int fl = (bx * G + by) * G + bz;

    atomicAdd(&g_cnt[fl], 1.0f);

    const float4* f4 = (const float4*)(feats + (size_t)i * INC);
    float4* dst = (float4*)(g_voxsum + (size_t)fl * INC);
#pragma unroll
    for (int k = 0; k < INC / 4; k++) {
        float4 v = f4[k];
        atomicAdd(dst + k, v);   // sm_90+ vector red.global.add.v4.f32
    }
}

// ============================================================================
// 2) normalize sums -> means (in place). empty voxels stay exactly 0.
// ============================================================================
__global__ void normalize_kernel() {
    int t = blockIdx.x * blockDim.x + threadIdx.x;   // one float4 per thread
    if (t >= NVOX * (INC / 4)) return;
    int vox = t >> 3;                                // INC/4 == 8
    float c = g_cnt[vox];
    float inv = 1.0f / fmaxf(c, 1.0f);
    float4* p = (float4*)g_voxsum + t;
    float4 v = *p;
    v.x *= inv; v.y *= inv; v.z *= inv; v.w *= inv;
    *p = v;
}

// ============================================================================
// 3) dense 3x3x3 conv, 32 -> 64 channels, SAME padding (zero)
//    EXACT R1 version (known-good ~650us): smem layout [dxy][zi][ci],
//    scalar broadcast LDS in the compute loop.
// ============================================================================
__global__ __launch_bounds__(128) void conv_kernel(const float* __restrict__ Wc) {
    __shared__ float sin_[3 * 3 * (TZ + 2) * INC];   // 20736 B

    const int x  = blockIdx.x;
    const int y  = blockIdx.y;
    const int z0 = blockIdx.z * TZ;
    const int t  = threadIdx.x;

    // cooperative halo load with zero padding
    for (int i = t; i < 3 * 3 * (TZ + 2) * INC; i += 128) {
        int ci  = i & (INC - 1);
        int rest = i >> 5;
        int zi  = rest % (TZ + 2); rest /= (TZ + 2);
        int dy  = rest % 3;
        int dx  = rest / 3;
        int gx = x + dx - 1, gy = y + dy - 1, gz = z0 + zi - 1;
        float v = 0.0f;
        if ((unsigned)gx < G && (unsigned)gy < G && (unsigned)gz < G)
            v = g_voxsum[(((size_t)(gx * G + gy) * G + gz) << 5) + ci];
        sin_[i] = v;
    }
    __syncthreads();

    const int co = t & (OUTC - 1);
    const int zb = (t >> 6) * 8;          // 0 or 8

    float acc[8];
#pragma unroll
    for (int z = 0; z < 8; z++) acc[z] = 0.0f;

#pragma unroll 1
    for (int dxy = 0; dxy < 9; dxy++) {
        const float* sp = sin_ + dxy * ((TZ + 2) * INC);
        const float* wp = Wc + (size_t)dxy * 3 * INC * OUTC + co;
#pragma unroll
        for (int ci = 0; ci < INC; ci++) {
            float r[10];
#pragma unroll
            for (int j = 0; j < 10; j++) r[j] = sp[(zb + j) * INC + ci];
#pragma unroll
            for (int dz = 0; dz < 3; dz++) {
                float w = wp[(size_t)(dz * INC + ci) * OUTC];
#pragma unroll
                for (int z = 0; z < 8; z++) acc[z] += r[z + dz] * w;
            }
        }
    }

    size_t obase = ((size_t)((x * G + y) * G + z0 + zb)) * OUTC + co;
#pragma unroll
    for (int z = 0; z < 8; z++) g_conv[obase + (size_t)z * OUTC] = acc[z];
}

// ============================================================================
// 4) trilinear devoxelize + residual linear (R3 version: two warps per point,
//    lane owns one output channel, W_lin in 32 registers, zero LDS).
// ============================================================================
__global__ __launch_bounds__(256) void devox_kernel(const float* __restrict__ pts,
                                                    const float* __restrict__ feats,
                                                    const float* __restrict__ Wlin,
                                                    const float* __restrict__ blin,
                                                    float* __restrict__ out, int n) {
    const int lane   = threadIdx.x & 31;
    const int gwarp  = (blockIdx.x * blockDim.x + threadIdx.x) >> 5;
    const int nwarps = (gridDim.x * blockDim.x) >> 5;
    const int h      = gwarp & 1;          // which half of the 64 channels
    const int co     = h * 32 + lane;

    // one W_lin row per lane: 32 registers
    float wreg[INC];
    {
        const float4* r0 = (const float4*)(Wlin + (size_t)co * INC);
#pragma unroll
        for (int k = 0; k < INC / 4; k++) {
            float4 a = r0[k];
            wreg[4 * k + 0] = a.x;
            wreg[4 * k + 1] = a.y;
            wreg[4 * k + 2] = a.z;
            wreg[4 * k + 3] = a.w;
        }
    }
    const float bl = blin[co];

    for (int pair = gwarp; pair < 2 * n; pair += nwarps) {
        int p = pair >> 1;   // h == pair & 1 (nwarps is even)

        float px = pts[3 * p + 0];
        float py = pts[3 * p + 1];
        float pz = pts[3 * p + 2];
        int bx = (int)floorf(px);
        int by = (int)floorf(py);
        int bz = (int)floorf(pz);
        float fx = px - (float)bx;
        float fy = py - (float)by;
        float fz = pz - (float)bz;

        float fv = feats[(size_t)p * INC + lane];

        float acc = bl;

#pragma unroll
        for (int c = 0; c < 8; c++) {
            int dx = (c >> 2) & 1, dy = (c >> 1) & 1, dz = c & 1;
            int nx = bx + dx, ny = by + dy, nz = bz + dz;
            float w = (dx ? fx : 1.0f - fx) * (dy ? fy : 1.0f - fy) * (dz ? fz : 1.0f - fz);
            if ((unsigned)nx < G && (unsigned)ny < G && (unsigned)nz < G) {
                int fl = (nx * G + ny) * G + nz;
                if (g_cnt[fl] > 0.0f) {
                    float v = g_conv[(size_t)fl * OUTC + co];   // 128B coalesced
                    acc += w * v;
                }
            }
        }

#pragma unroll
        for (int ci = 0; ci < INC; ci++) {
            float f = __shfl_sync(0xffffffffu, fv, ci);
            acc += f * wreg[ci];
        }

        out[(size_t)p * OUTC + co] = acc;
    }
}

// ============================================================================
extern "C" void kernel_launch(void* const* d_in, const int* in_sizes, int n_in,
                              void* d_out, int out_size) {
    const float* pts   = (const float*)d_in[0];
    const float* feats = (const float*)d_in[1];
    const float* Wc    = (const float*)d_in[2];
    const float* Wl    = (const float*)d_in[3];
    const float* bl    = (const float*)d_in[4];
    float* out = (float*)d_out;
    int npts = in_sizes[0] / 3;

    void *p_sum = nullptr, *p_cnt = nullptr;
    cudaGetSymbolAddress(&p_sum, g_voxsum);
    cudaGetSymbolAddress(&p_cnt, g_cnt);
    cudaMemsetAsync(p_sum, 0, (size_t)NVOX * INC * sizeof(float));
    cudaMemsetAsync(p_cnt, 0, (size_t)NVOX * sizeof(float));

    scatter_kernel<<<(npts + 255) / 256, 256>>>(pts, feats, npts);

    normalize_kernel<<<(NVOX * (INC / 4) + 255) / 256, 256>>>();

    dim3 cgrid(G, G, G / TZ);
    conv_kernel<<<cgrid, 128>>>(Wc);

    devox_kernel<<<4096, 256>>>(pts, feats, Wl, bl, out, npts);
}

// round 5
// speedup vs baseline: 1.7599x; 1.7599x over previous
#include <cuda_runtime.h>
#include <cuda_bf16.h>

#define G     64
#define NVOX  (G*G*G)
#define INC   32
#define OUTC  64
#define TZ    16

// ---- device scratch (allocation-free rule: static __device__ arrays) ----
__device__ float g_voxsum[NVOX * INC];   // 32 MB: scatter sums, normalized in place
__device__ float g_cnt[NVOX];            //  1 MB: per-voxel point counts
__device__ float g_conv[NVOX * OUTC];    // 64 MB: conv output (occupancy-masked)

// ============================================================================
// 1) scatter-mean accumulate: per point, vector atomics into its voxel
// ============================================================================
__global__ void scatter_kernel(const float* __restrict__ pts,
                               const float* __restrict__ feats, int n) {
    int i = blockIdx.x * blockDim.x + threadIdx.x;
    if (i >= n) return;
    float px = pts[3 * i + 0];
    float py = pts[3 * i + 1];
    float pz = pts[3 * i + 2];
    int bx = (int)floorf(px);
    int by = (int)floorf(py);
    int bz = (int)floorf(pz);
    bx = min(max(bx, 0), G - 1);
    by = min(max(by, 0), G - 1);
    bz = min(max(bz, 0), G - 1);
    int fl = (bx * G + by) * G + bz;

    atomicAdd(&g_cnt[fl], 1.0f);

    const float4* f4 = (const float4*)(feats + (size_t)i * INC);
    float4* dst = (float4*)(g_voxsum + (size_t)fl * INC);
#pragma unroll
    for (int k = 0; k < INC / 4; k++) {
        float4 v = f4[k];
        atomicAdd(dst + k, v);   // sm_90+ vector red.global.add.v4.f32
    }
}

// ============================================================================
// 2) normalize sums -> means (in place). empty voxels stay exactly 0.
// ============================================================================
__global__ void normalize_kernel() {
    int t = blockIdx.x * blockDim.x + threadIdx.x;   // one float4 per thread
    if (t >= NVOX * (INC / 4)) return;
    int vox = t >> 3;                                // INC/4 == 8
    float c = g_cnt[vox];
    float inv = 1.0f / fmaxf(c, 1.0f);
    float4* p = (float4*)g_voxsum + t;
    float4 v = *p;
    v.x *= inv; v.y *= inv; v.z *= inv; v.w *= inv;
    *p = v;
}

// ============================================================================
// 3) dense 3x3x3 conv, 32 -> 64 channels, SAME padding (zero). R1 structure.
//    Epilogue now multiplies by occupancy (cnt>0), so devox never reads g_cnt:
//    w*occ*conv == w*(occ*conv) exactly since occ is 0.0 or 1.0.
// ============================================================================
__global__ __launch_bounds__(128) void conv_kernel(const float* __restrict__ Wc) {
    __shared__ float sin_[3 * 3 * (TZ + 2) * INC];   // 20736 B

    const int x  = blockIdx.x;
    const int y  = blockIdx.y;
    const int z0 = blockIdx.z * TZ;
    const int t  = threadIdx.x;

    // cooperative halo load with zero padding
    for (int i = t; i < 3 * 3 * (TZ + 2) * INC; i += 128) {
        int ci  = i & (INC - 1);
        int rest = i >> 5;
        int zi  = rest % (TZ + 2); rest /= (TZ + 2);
        int dy  = rest % 3;
        int dx  = rest / 3;
        int gx = x + dx - 1, gy = y + dy - 1, gz = z0 + zi - 1;
        float v = 0.0f;
        if ((unsigned)gx < G && (unsigned)gy < G && (unsigned)gz < G)
            v = g_voxsum[(((size_t)(gx * G + gy) * G + gz) << 5) + ci];
        sin_[i] = v;
    }
    __syncthreads();

    const int co = t & (OUTC - 1);
    const int zb = (t >> 6) * 8;          // 0 or 8

    float acc[8];
#pragma unroll
    for (int z = 0; z < 8; z++) acc[z] = 0.0f;

#pragma unroll 1
    for (int dxy = 0; dxy < 9; dxy++) {
        const float* sp = sin_ + dxy * ((TZ + 2) * INC);
        const float* wp = Wc + (size_t)dxy * 3 * INC * OUTC + co;
#pragma unroll
        for (int ci = 0; ci < INC; ci++) {
            float r[10];
#pragma unroll
            for (int j = 0; j < 10; j++) r[j] = sp[(zb + j) * INC + ci];
#pragma unroll
            for (int dz = 0; dz < 3; dz++) {
                float w = wp[(size_t)(dz * INC + ci) * OUTC];
#pragma unroll
                for (int z = 0; z < 8; z++) acc[z] += r[z + dz] * w;
            }
        }
    }

    int vbase = (x * G + y) * G + z0 + zb;
    size_t obase = (size_t)vbase * OUTC + co;
#pragma unroll
    for (int z = 0; z < 8; z++) {
        float occ = (g_cnt[vbase + z] > 0.0f) ? 1.0f : 0.0f;  // broadcast load
        g_conv[obase + (size_t)z * OUTC] = acc[z] * occ;
    }
}

// ============================================================================
// 4a) residual linear: out = b + feats @ W_lin^T.
//     warp handles (point, half); lane owns co = half*32+lane; W row in 32
//     regs loaded once per warp (amortized over grid-stride iterations).
// ============================================================================
__global__ __launch_bounds__(256) void residual_kernel(const float* __restrict__ feats,
                                                       const float* __restrict__ Wlin,
                                                       const float* __restrict__ blin,
                                                       float* __restrict__ out, int n) {
    const int lane   = threadIdx.x & 31;
    const int gwarp  = (blockIdx.x * blockDim.x + threadIdx.x) >> 5;
    const int nwarps = (gridDim.x * blockDim.x) >> 5;
    const int h      = gwarp & 1;
    const int co     = h * 32 + lane;

    float wreg[INC];
    {
        const float4* r0 = (const float4*)(Wlin + (size_t)co * INC);
#pragma unroll
        for (int k = 0; k < INC / 4; k++) {
            float4 a = r0[k];
            wreg[4 * k + 0] = a.x;
            wreg[4 * k + 1] = a.y;
            wreg[4 * k + 2] = a.z;
            wreg[4 * k + 3] = a.w;
        }
    }
    const float bl = blin[co];

    for (int pair = gwarp; pair < 2 * n; pair += nwarps) {
        int p = pair >> 1;   // h == pair & 1 (nwarps is even)
        float fv = feats[(size_t)p * INC + lane];
        float acc = bl;
#pragma unroll
        for (int ci = 0; ci < INC; ci++) {
            float f = __shfl_sync(0xffffffffu, fv, ci);
            acc += f * wreg[ci];
        }
        out[(size_t)p * OUTC + co] = acc;
    }
}

// ============================================================================
// 4b) trilinear devoxelize: gathers only, accumulating onto the residual
//     already sitting in out. R1 shape: one warp per point, float2 per lane.
// ============================================================================
__global__ __launch_bounds__(256) void devox_kernel(const float* __restrict__ pts,
                                                    float* __restrict__ out, int n) {
    const int lane   = threadIdx.x & 31;
    const int warp   = (blockIdx.x * blockDim.x + threadIdx.x) >> 5;
    const int nwarps = (gridDim.x * blockDim.x) >> 5;

    for (int p = warp; p < n; p += nwarps) {
        float px = pts[3 * p + 0];
        float py = pts[3 * p + 1];
        float pz = pts[3 * p + 2];
        int bx = (int)floorf(px);
        int by = (int)floorf(py);
        int bz = (int)floorf(pz);
        float fx = px - (float)bx;
        float fy = py - (float)by;
        float fz = pz - (float)bz;

        float2* orow = (float2*)out + (size_t)p * (OUTC / 2);
        float2 acc = orow[lane];

#pragma unroll
        for (int c = 0; c < 8; c++) {
            int dx = (c >> 2) & 1, dy = (c >> 1) & 1, dz = c & 1;
            int nx = bx + dx, ny = by + dy, nz = bz + dz;
            float w = (dx ? fx : 1.0f - fx) * (dy ? fy : 1.0f - fy) * (dz ? fz : 1.0f - fz);
            if ((unsigned)nx < G && (unsigned)ny < G && (unsigned)nz < G) {
                int fl = (nx * G + ny) * G + nz;
                const float2* row = (const float2*)(g_conv + (size_t)fl * OUTC);
                float2 v = row[lane];     // occupancy already folded into g_conv
                acc.x += w * v.x;
                acc.y += w * v.y;
            }
        }

        orow[lane] = acc;
    }
}

// ============================================================================
extern "C" void kernel_launch(void* const* d_in, const int* in_sizes, int n_in,
                              void* d_out, int out_size) {
    const float* pts   = (const float*)d_in[0];
    const float* feats = (const float*)d_in[1];
    const float* Wc    = (const float*)d_in[2];
    const float* Wl    = (const float*)d_in[3];
    const float* bl    = (const float*)d_in[4];
    float* out = (float*)d_out;
    int npts = in_sizes[0] / 3;

    void *p_sum = nullptr, *p_cnt = nullptr;
    cudaGetSymbolAddress(&p_sum, g_voxsum);
    cudaGetSymbolAddress(&p_cnt, g_cnt);
    cudaMemsetAsync(p_sum, 0, (size_t)NVOX * INC * sizeof(float));
    cudaMemsetAsync(p_cnt, 0, (size_t)NVOX * sizeof(float));

    scatter_kernel<<<(npts + 255) / 256, 256>>>(pts, feats, npts);

    normalize_kernel<<<(NVOX * (INC / 4) + 255) / 256, 256>>>();

    dim3 cgrid(G, G, G / TZ);
    conv_kernel<<<cgrid, 128>>>(Wc);

    residual_kernel<<<2048, 256>>>(feats, Wl, bl, out, npts);

    devox_kernel<<<4096, 256>>>(pts, out, npts);
}